// round 1
// baseline (speedup 1.0000x reference)
#include <cuda_runtime.h>
#include <math.h>

// Problem constants (fixed by the reference)
#define BATCH 8
#define SEQ   2048
#define EMBED 1024
#define BS    (BATCH * SEQ)     // 16384 rows for QKV projection

// Device-global scratch (no allocations allowed in kernel_launch).
// Q, K, V: [BS, EMBED] fp32 each (64 MB each). S: [BATCH, SEQ, SEQ] fp32 (128 MB).
__device__ float g_Q[(size_t)BS * EMBED];
__device__ float g_K[(size_t)BS * EMBED];
__device__ float g_V[(size_t)BS * EMBED];
__device__ float g_S[(size_t)BATCH * SEQ * SEQ];

// ---------------------------------------------------------------------------
// GEMM NT:  C[M,N] = alpha * A[M,K] * B[N,K]^T  (+ bias[N] if HAS_BIAS)
// Both operands row-major with the K (reduction) dimension contiguous.
// Tile: 128x128x8, 256 threads, 8x8 per-thread micro-tile.
// Batched via blockIdx.z with element strides sA/sB/sC.
// ---------------------------------------------------------------------------
template <bool HAS_BIAS>
__global__ __launch_bounds__(256, 1)
void gemm_nt(const float* __restrict__ A, const float* __restrict__ Bm,
             const float* __restrict__ bias, float* __restrict__ C,
             int M, int N, int K, float alpha,
             long long sA, long long sB, long long sC)
{
    A  += (long long)blockIdx.z * sA;
    Bm += (long long)blockIdx.z * sB;
    C  += (long long)blockIdx.z * sC;

    __shared__ float As[8][128];
    __shared__ float Bs[8][128];

    const int tid = threadIdx.x;
    const int tx = tid & 15;          // 0..15  -> N direction
    const int ty = tid >> 4;          // 0..15  -> M direction

    const int rowA0 = blockIdx.y * 128;
    const int colB0 = blockIdx.x * 128;

    // Load mapping: each thread loads one float4 of A and one of B per k-tile
    const int la_r = tid >> 1;         // 0..127 (row within tile)
    const int la_k = (tid & 1) * 4;    // 0 or 4 (k offset)

    const float* aptr = A  + (long long)(rowA0 + la_r) * K + la_k;
    const float* bptr = Bm + (long long)(colB0 + la_r) * K + la_k;

    float acc[8][8];
#pragma unroll
    for (int i = 0; i < 8; i++)
#pragma unroll
        for (int j = 0; j < 8; j++) acc[i][j] = 0.f;

    for (int kt = 0; kt < K; kt += 8) {
        float4 av = *(const float4*)(aptr + kt);
        float4 bv = *(const float4*)(bptr + kt);
        As[la_k + 0][la_r] = av.x;
        As[la_k + 1][la_r] = av.y;
        As[la_k + 2][la_r] = av.z;
        As[la_k + 3][la_r] = av.w;
        Bs[la_k + 0][la_r] = bv.x;
        Bs[la_k + 1][la_r] = bv.y;
        Bs[la_k + 2][la_r] = bv.z;
        Bs[la_k + 3][la_r] = bv.w;
        __syncthreads();

#pragma unroll
        for (int kk = 0; kk < 8; kk++) {
            float a[8], b[8];
            *(float4*)(a + 0) = *(const float4*)(&As[kk][ty * 8 + 0]);
            *(float4*)(a + 4) = *(const float4*)(&As[kk][ty * 8 + 4]);
            *(float4*)(b + 0) = *(const float4*)(&Bs[kk][tx * 8 + 0]);
            *(float4*)(b + 4) = *(const float4*)(&Bs[kk][tx * 8 + 4]);
#pragma unroll
            for (int i = 0; i < 8; i++)
#pragma unroll
                for (int j = 0; j < 8; j++)
                    acc[i][j] = fmaf(a[i], b[j], acc[i][j]);
        }
        __syncthreads();
    }

    float bvals[8];
    if (HAS_BIAS) {
        *(float4*)(bvals + 0) = *(const float4*)(bias + colB0 + tx * 8 + 0);
        *(float4*)(bvals + 4) = *(const float4*)(bias + colB0 + tx * 8 + 4);
    }

#pragma unroll
    for (int i = 0; i < 8; i++) {
        float* crow = C + (long long)(rowA0 + ty * 8 + i) * N + colB0 + tx * 8;
#pragma unroll
        for (int j = 0; j < 8; j += 4) {
            float4 v;
            v.x = acc[i][j + 0] * alpha;
            v.y = acc[i][j + 1] * alpha;
            v.z = acc[i][j + 2] * alpha;
            v.w = acc[i][j + 3] * alpha;
            if (HAS_BIAS) {
                v.x += bvals[j + 0];
                v.y += bvals[j + 1];
                v.z += bvals[j + 2];
                v.w += bvals[j + 3];
            }
            *(float4*)(crow + j) = v;
        }
    }
}

// ---------------------------------------------------------------------------
// GEMM NN:  C[M,N] = A[M,K] * B[K,N]   (A: k-contiguous, B: n-contiguous)
// Used for out = weights @ V.
// ---------------------------------------------------------------------------
__global__ __launch_bounds__(256, 1)
void gemm_nn(const float* __restrict__ A, const float* __restrict__ Bm,
             float* __restrict__ C,
             int M, int N, int K,
             long long sA, long long sB, long long sC)
{
    A  += (long long)blockIdx.z * sA;
    Bm += (long long)blockIdx.z * sB;
    C  += (long long)blockIdx.z * sC;

    __shared__ float As[8][128];
    __shared__ float Bs[8][128];

    const int tid = threadIdx.x;
    const int tx = tid & 15;
    const int ty = tid >> 4;

    const int rowA0 = blockIdx.y * 128;
    const int colB0 = blockIdx.x * 128;

    const int la_r = tid >> 1;         // A row within tile
    const int la_k = (tid & 1) * 4;    // A k offset

    const int lb_k = tid >> 5;         // 0..7   (B row = k)
    const int lb_n = (tid & 31) * 4;   // 0..124 (B col)

    const float* aptr = A  + (long long)(rowA0 + la_r) * K + la_k;
    const float* bptr = Bm + colB0 + lb_n + (long long)lb_k * N;

    float acc[8][8];
#pragma unroll
    for (int i = 0; i < 8; i++)
#pragma unroll
        for (int j = 0; j < 8; j++) acc[i][j] = 0.f;

    for (int kt = 0; kt < K; kt += 8) {
        float4 av = *(const float4*)(aptr + kt);
        float4 bv = *(const float4*)(bptr + (long long)kt * N);
        As[la_k + 0][la_r] = av.x;
        As[la_k + 1][la_r] = av.y;
        As[la_k + 2][la_r] = av.z;
        As[la_k + 3][la_r] = av.w;
        *(float4*)(&Bs[lb_k][lb_n]) = bv;
        __syncthreads();

#pragma unroll
        for (int kk = 0; kk < 8; kk++) {
            float a[8], b[8];
            *(float4*)(a + 0) = *(const float4*)(&As[kk][ty * 8 + 0]);
            *(float4*)(a + 4) = *(const float4*)(&As[kk][ty * 8 + 4]);
            *(float4*)(b + 0) = *(const float4*)(&Bs[kk][tx * 8 + 0]);
            *(float4*)(b + 4) = *(const float4*)(&Bs[kk][tx * 8 + 4]);
#pragma unroll
            for (int i = 0; i < 8; i++)
#pragma unroll
                for (int j = 0; j < 8; j++)
                    acc[i][j] = fmaf(a[i], b[j], acc[i][j]);
        }
        __syncthreads();
    }

#pragma unroll
    for (int i = 0; i < 8; i++) {
        float* crow = C + (long long)(rowA0 + ty * 8 + i) * N + colB0 + tx * 8;
#pragma unroll
        for (int j = 0; j < 8; j += 4) {
            float4 v;
            v.x = acc[i][j + 0];
            v.y = acc[i][j + 1];
            v.z = acc[i][j + 2];
            v.w = acc[i][j + 3];
            *(float4*)(crow + j) = v;
        }
    }
}

// ---------------------------------------------------------------------------
// Row softmax in place: one block per row of SEQ=2048 floats, 256 threads.
// ---------------------------------------------------------------------------
__global__ __launch_bounds__(256, 4)
void softmax_rows(float* __restrict__ Sm)
{
    float* row = Sm + (long long)blockIdx.x * SEQ;
    const int t = threadIdx.x;

    float v[8];
    *(float4*)(v + 0) = *(const float4*)(row + t * 8 + 0);
    *(float4*)(v + 4) = *(const float4*)(row + t * 8 + 4);

    float mx = v[0];
#pragma unroll
    for (int i = 1; i < 8; i++) mx = fmaxf(mx, v[i]);

    __shared__ float red[256];
    red[t] = mx;
    __syncthreads();
#pragma unroll
    for (int s = 128; s > 0; s >>= 1) {
        if (t < s) red[t] = fmaxf(red[t], red[t + s]);
        __syncthreads();
    }
    mx = red[0];
    __syncthreads();

    float sum = 0.f;
#pragma unroll
    for (int i = 0; i < 8; i++) {
        v[i] = __expf(v[i] - mx);
        sum += v[i];
    }
    red[t] = sum;
    __syncthreads();
#pragma unroll
    for (int s = 128; s > 0; s >>= 1) {
        if (t < s) red[t] += red[t + s];
        __syncthreads();
    }
    const float inv = 1.f / red[0];

#pragma unroll
    for (int i = 0; i < 8; i++) v[i] *= inv;
    *(float4*)(row + t * 8 + 0) = *(const float4*)(v + 0);
    *(float4*)(row + t * 8 + 4) = *(const float4*)(v + 4);
}

// ---------------------------------------------------------------------------
// Launch: QKV projections -> scores -> softmax -> A*V
// ---------------------------------------------------------------------------
extern "C" void kernel_launch(void* const* d_in, const int* in_sizes, int n_in,
                              void* d_out, int out_size)
{
    const float* x  = (const float*)d_in[0];
    const float* Wq = (const float*)d_in[1];
    const float* bq = (const float*)d_in[2];
    const float* Wk = (const float*)d_in[3];
    const float* bk = (const float*)d_in[4];
    const float* Wv = (const float*)d_in[5];
    const float* bv = (const float*)d_in[6];
    float* out = (float*)d_out;

    float *Qp, *Kp, *Vp, *Sp;
    cudaGetSymbolAddress((void**)&Qp, g_Q);
    cudaGetSymbolAddress((void**)&Kp, g_K);
    cudaGetSymbolAddress((void**)&Vp, g_V);
    cudaGetSymbolAddress((void**)&Sp, g_S);

    const dim3 blk(256);
    const float scale = 1.0f / sqrtf((float)EMBED);

    // 1) QKV projections: [BS, EMBED] x [EMBED, EMBED]^T + bias
    {
        dim3 grid(EMBED / 128, BS / 128, 1);   // (8, 128)
        gemm_nt<true><<<grid, blk>>>(x, Wq, bq, Qp, BS, EMBED, EMBED, 1.0f, 0, 0, 0);
        gemm_nt<true><<<grid, blk>>>(x, Wk, bk, Kp, BS, EMBED, EMBED, 1.0f, 0, 0, 0);
        gemm_nt<true><<<grid, blk>>>(x, Wv, bv, Vp, BS, EMBED, EMBED, 1.0f, 0, 0, 0);
    }

    // 2) scores = scale * Q @ K^T, batched over BATCH
    {
        dim3 grid(SEQ / 128, SEQ / 128, BATCH);   // (16, 16, 8)
        gemm_nt<false><<<grid, blk>>>(Qp, Kp, nullptr, Sp,
                                      SEQ, SEQ, EMBED, scale,
                                      (long long)SEQ * EMBED,
                                      (long long)SEQ * EMBED,
                                      (long long)SEQ * SEQ);
    }

    // 3) softmax over last dim, in place
    softmax_rows<<<BATCH * SEQ, blk>>>(Sp);

    // 4) out = weights @ V, batched
    {
        dim3 grid(EMBED / 128, SEQ / 128, BATCH);  // (8, 16, 8)
        gemm_nn<<<grid, blk>>>(Sp, Vp, out,
                               SEQ, EMBED, SEQ,
                               (long long)SEQ * SEQ,
                               (long long)SEQ * EMBED,
                               (long long)SEQ * EMBED);
    }
}

// round 3
// speedup vs baseline: 3.2405x; 3.2405x over previous
#include <cuda_runtime.h>
#include <cuda_bf16.h>
#include <cstdint>
#include <math.h>

// ---------------------------------------------------------------------------
// Problem constants
// ---------------------------------------------------------------------------
#define BATCH 8
#define SEQ   2048
#define EMBED 1024
#define BS    (BATCH * SEQ)          // 16384

// ---------------------------------------------------------------------------
// Device-global scratch (allocation-free rule)
// ---------------------------------------------------------------------------
__device__ __nv_bfloat16 g_xh[(size_t)BS * EMBED];
__device__ __nv_bfloat16 g_xl[(size_t)BS * EMBED];
__device__ __nv_bfloat16 g_Wqh[EMBED * EMBED], g_Wql[EMBED * EMBED];
__device__ __nv_bfloat16 g_Wkh[EMBED * EMBED], g_Wkl[EMBED * EMBED];
__device__ __nv_bfloat16 g_Wvh[EMBED * EMBED], g_Wvl[EMBED * EMBED];
__device__ __nv_bfloat16 g_Qh[(size_t)BS * EMBED], g_Ql[(size_t)BS * EMBED];
__device__ __nv_bfloat16 g_Kh[(size_t)BS * EMBED], g_Kl[(size_t)BS * EMBED];
// V stored pre-transposed: [EMBED rows][BS cols] (per-batch window of 2048 cols)
__device__ __nv_bfloat16 g_Vth[(size_t)EMBED * BS], g_Vtl[(size_t)EMBED * BS];
__device__ float         g_S[(size_t)BATCH * SEQ * SEQ];
__device__ __nv_bfloat16 g_Ph[(size_t)BATCH * SEQ * SEQ], g_Pl[(size_t)BATCH * SEQ * SEQ];

// ---------------------------------------------------------------------------
// Helpers
// ---------------------------------------------------------------------------
__device__ __forceinline__ uint32_t smem_u32(const void* p) {
    uint32_t a;
    asm("{ .reg .u64 t; cvta.to.shared.u64 t, %1; cvt.u32.u64 %0, t; }" : "=r"(a) : "l"(p));
    return a;
}

#define CP_ASYNC16(sm, gp) \
    asm volatile("cp.async.cg.shared.global [%0], [%1], 16;" :: "r"(sm), "l"(gp) : "memory")
#define CP_COMMIT()  asm volatile("cp.async.commit_group;" ::: "memory")
#define CP_WAIT0()   asm volatile("cp.async.wait_group 0;" ::: "memory")
#define CP_WAIT1()   asm volatile("cp.async.wait_group 1;" ::: "memory")

__device__ __forceinline__ void ldsm_x4(uint32_t* r, uint32_t addr) {
    asm volatile("ldmatrix.sync.aligned.m8n8.x4.shared.b16 {%0,%1,%2,%3}, [%4];"
                 : "=r"(r[0]), "=r"(r[1]), "=r"(r[2]), "=r"(r[3]) : "r"(addr));
}

__device__ __forceinline__ void mma16816(float* c, const uint32_t* a, const uint32_t* b) {
    asm volatile(
        "mma.sync.aligned.m16n8k16.row.col.f32.bf16.bf16.f32 "
        "{%0,%1,%2,%3}, {%4,%5,%6,%7}, {%8,%9}, {%0,%1,%2,%3};"
        : "+f"(c[0]), "+f"(c[1]), "+f"(c[2]), "+f"(c[3])
        : "r"(a[0]), "r"(a[1]), "r"(a[2]), "r"(a[3]), "r"(b[0]), "r"(b[1]));
}

// byte offset of 16B chunk (row, c) inside a [rows][64 bf16] tile, xor-swizzled
__device__ __forceinline__ uint32_t swz(int row, int c) {
    return (uint32_t)((row * 8 + (c ^ (row & 7))) * 16);
}

// ---------------------------------------------------------------------------
// HMMA GEMM NT: C[M,N] = A[M,K] * B[N,K]^T, two-term bf16 split operands
//   D += AhBh + AhBl + AlBh (fp32 accum in registers)
// Tile 128x128, K-chunk 64, 256 threads (warps 4x2 -> 32x64 warp tiles),
// double-buffered cp.async SMEM pipeline.
// MODE 0: C = fp32 -> Cf
// MODE 1: v = (acc + bias[col]) * scale; split -> Ch/Cl (bf16)
// MODE 2: v = (acc + bias[row]) * scale; split -> Ch/Cl (bf16)
// ---------------------------------------------------------------------------
#define STAGE_BYTES 65536
#define A_H_OFF 0
#define A_L_OFF 16384
#define B_H_OFF 32768
#define B_L_OFF 49152
#define GEMM_SMEM (2 * STAGE_BYTES)

template <int MODE>
__global__ void __launch_bounds__(256, 1)
gemm_tc(const __nv_bfloat16* __restrict__ Ah, const __nv_bfloat16* __restrict__ Al,
        const __nv_bfloat16* __restrict__ Bh, const __nv_bfloat16* __restrict__ Bl,
        const float* __restrict__ bias, float scale,
        float* __restrict__ Cf, __nv_bfloat16* __restrict__ Ch, __nv_bfloat16* __restrict__ Cl,
        int lda, int ldb, int ldc, int nchunk,
        long long strideA, long long strideB, long long strideC)
{
    extern __shared__ char smem[];
    const uint32_t sbase = smem_u32(smem);
    const int tid = threadIdx.x;
    const int wid = tid >> 5;
    const int lane = tid & 31;
    const int wm = wid & 3;          // 0..3  M direction (32 rows each)
    const int wn = wid >> 2;         // 0..1  N direction (64 cols each)

    const long long z = blockIdx.z;
    Ah += z * strideA;  Al += z * strideA;
    Bh += z * strideB;  Bl += z * strideB;

    const int rowA0 = blockIdx.y * 128;
    const int colB0 = blockIdx.x * 128;

    // loader mapping: 1024 16B chunks per operand tile, 4 per thread
    const int lr = tid >> 1;              // not used; use idx mapping below

    float acc[2][8][4];
#pragma unroll
    for (int mt = 0; mt < 2; mt++)
#pragma unroll
        for (int nt = 0; nt < 8; nt++)
#pragma unroll
            for (int r = 0; r < 4; r++) acc[mt][nt][r] = 0.f;

    // global base pointers for this block
    const __nv_bfloat16* gAh = Ah + (size_t)rowA0 * lda;
    const __nv_bfloat16* gAl = Al + (size_t)rowA0 * lda;
    const __nv_bfloat16* gBh = Bh + (size_t)colB0 * ldb;
    const __nv_bfloat16* gBl = Bl + (size_t)colB0 * ldb;

    // issue all cp.async for one stage
    auto issue_stage = [&](int kc, int stg) {
        const uint32_t sb = sbase + stg * STAGE_BYTES;
        const int k0 = kc * 64;
#pragma unroll
        for (int it = 0; it < 4; it++) {
            int idx = it * 256 + tid;
            int r = idx >> 3, c = idx & 7;
            uint32_t so = swz(r, c);
            CP_ASYNC16(sb + A_H_OFF + so, gAh + (size_t)r * lda + k0 + c * 8);
            CP_ASYNC16(sb + A_L_OFF + so, gAl + (size_t)r * lda + k0 + c * 8);
            CP_ASYNC16(sb + B_H_OFF + so, gBh + (size_t)r * ldb + k0 + c * 8);
            CP_ASYNC16(sb + B_L_OFF + so, gBl + (size_t)r * ldb + k0 + c * 8);
        }
    };

    issue_stage(0, 0);
    CP_COMMIT();

    // ldmatrix lane address components
    const int a_row = lane & 15;              // row within 16-row m-tile
    const int a_csel = lane >> 4;             // 0/1 -> k chunk within k-step
    const int b_row = (lane & 7) + ((lane >> 4) << 3);  // row within 16-row n-tile
    const int b_csel = (lane >> 3) & 1;

    for (int kc = 0; kc < nchunk; kc++) {
        const int stg = kc & 1;
        if (kc + 1 < nchunk) {
            issue_stage(kc + 1, stg ^ 1);
            CP_COMMIT();
            CP_WAIT1();
        } else {
            CP_WAIT0();
        }
        __syncthreads();

        const uint32_t sb = sbase + stg * STAGE_BYTES;
        const uint32_t aH = sb + A_H_OFF, aL = sb + A_L_OFF;
        const uint32_t bH = sb + B_H_OFF, bL = sb + B_L_OFF;

#pragma unroll
        for (int ks = 0; ks < 4; ks++) {
            uint32_t fAh[2][4], fAl[2][4], fBh[4][4], fBl[4][4];
            const int kchunk = ks * 2;
#pragma unroll
            for (int mt = 0; mt < 2; mt++) {
                int mr = wm * 32 + mt * 16 + a_row;
                uint32_t off = swz(mr, kchunk + a_csel);
                ldsm_x4(fAh[mt], aH + off);
                ldsm_x4(fAl[mt], aL + off);
            }
#pragma unroll
            for (int g = 0; g < 4; g++) {
                int nr = wn * 64 + g * 16 + b_row;
                uint32_t off = swz(nr, kchunk + b_csel);
                ldsm_x4(fBh[g], bH + off);
                ldsm_x4(fBl[g], bL + off);
            }
#pragma unroll
            for (int mt = 0; mt < 2; mt++)
#pragma unroll
                for (int nt = 0; nt < 8; nt++) {
                    const uint32_t* bh = &fBh[nt >> 1][(nt & 1) * 2];
                    const uint32_t* bl = &fBl[nt >> 1][(nt & 1) * 2];
                    mma16816(acc[mt][nt], fAh[mt], bh);
                    mma16816(acc[mt][nt], fAh[mt], bl);
                    mma16816(acc[mt][nt], fAl[mt], bh);
                }
        }
        __syncthreads();
    }

    // ------------------------------ epilogue ------------------------------
    const int lrow = (lane >> 2);        // 0..7
    const int lcol = (lane & 3) * 2;     // 0,2,4,6

#pragma unroll
    for (int mt = 0; mt < 2; mt++) {
#pragma unroll
        for (int half = 0; half < 2; half++) {     // half 0: regs {0,1}; half 1: regs {2,3}
            const int row = rowA0 + wm * 32 + mt * 16 + lrow + half * 8;
            float rb = (MODE == 2) ? bias[row] : 0.f;
#pragma unroll
            for (int nt = 0; nt < 8; nt++) {
                const int col = colB0 + wn * 64 + nt * 8 + lcol;
                float v0 = acc[mt][nt][half * 2 + 0];
                float v1 = acc[mt][nt][half * 2 + 1];
                if (MODE == 0) {
                    float2 o = make_float2(v0, v1);
                    *(float2*)(Cf + z * strideC + (size_t)row * ldc + col) = o;
                } else {
                    if (MODE == 1) { v0 = (v0 + bias[col]) * scale; v1 = (v1 + bias[col + 1]) * scale; }
                    else           { v0 = (v0 + rb) * scale;       v1 = (v1 + rb) * scale; }
                    __nv_bfloat16 h0 = __float2bfloat16(v0);
                    __nv_bfloat16 h1 = __float2bfloat16(v1);
                    __nv_bfloat16 l0 = __float2bfloat16(v0 - __bfloat162float(h0));
                    __nv_bfloat16 l1 = __float2bfloat16(v1 - __bfloat162float(h1));
                    uint32_t hw = (uint32_t)__bfloat16_as_ushort(h0) |
                                  ((uint32_t)__bfloat16_as_ushort(h1) << 16);
                    uint32_t lw = (uint32_t)__bfloat16_as_ushort(l0) |
                                  ((uint32_t)__bfloat16_as_ushort(l1) << 16);
                    *(uint32_t*)(Ch + (size_t)row * ldc + col) = hw;
                    *(uint32_t*)(Cl + (size_t)row * ldc + col) = lw;
                }
            }
        }
    }
}

// ---------------------------------------------------------------------------
// fp32 -> (bf16 hi, bf16 lo) split
// ---------------------------------------------------------------------------
__global__ void __launch_bounds__(256, 8)
split_kernel(const float* __restrict__ in, __nv_bfloat16* __restrict__ hi,
             __nv_bfloat16* __restrict__ lo, size_t n)
{
    size_t i = ((size_t)blockIdx.x * blockDim.x + threadIdx.x) * 8;
    if (i >= n) return;
    float4 a = *(const float4*)(in + i);
    float4 b = *(const float4*)(in + i + 4);
    float v[8] = {a.x, a.y, a.z, a.w, b.x, b.y, b.z, b.w};
    alignas(16) uint32_t hw[4], lw[4];
#pragma unroll
    for (int c = 0; c < 8; c += 2) {
        __nv_bfloat16 h0 = __float2bfloat16(v[c]);
        __nv_bfloat16 h1 = __float2bfloat16(v[c + 1]);
        __nv_bfloat16 l0 = __float2bfloat16(v[c] - __bfloat162float(h0));
        __nv_bfloat16 l1 = __float2bfloat16(v[c + 1] - __bfloat162float(h1));
        hw[c >> 1] = (uint32_t)__bfloat16_as_ushort(h0) | ((uint32_t)__bfloat16_as_ushort(h1) << 16);
        lw[c >> 1] = (uint32_t)__bfloat16_as_ushort(l0) | ((uint32_t)__bfloat16_as_ushort(l1) << 16);
    }
    *(uint4*)(hi + i) = *(const uint4*)(&hw[0]);
    *(uint4*)(lo + i) = *(const uint4*)(&lw[0]);
}

// ---------------------------------------------------------------------------
// Row softmax (fp32 in) -> split bf16 out. One block per row of SEQ floats.
// ---------------------------------------------------------------------------
__global__ void __launch_bounds__(256, 4)
softmax_split(const float* __restrict__ Sm, __nv_bfloat16* __restrict__ Ph,
              __nv_bfloat16* __restrict__ Pl)
{
    const float* row = Sm + (size_t)blockIdx.x * SEQ;
    const int t = threadIdx.x;

    float v[8];
    *(float4*)(v + 0) = *(const float4*)(row + t * 8 + 0);
    *(float4*)(v + 4) = *(const float4*)(row + t * 8 + 4);

    float mx = v[0];
#pragma unroll
    for (int i = 1; i < 8; i++) mx = fmaxf(mx, v[i]);

    __shared__ float red[256];
    red[t] = mx;
    __syncthreads();
#pragma unroll
    for (int s = 128; s > 0; s >>= 1) {
        if (t < s) red[t] = fmaxf(red[t], red[t + s]);
        __syncthreads();
    }
    mx = red[0];
    __syncthreads();

    float sum = 0.f;
#pragma unroll
    for (int i = 0; i < 8; i++) {
        v[i] = __expf(v[i] - mx);
        sum += v[i];
    }
    red[t] = sum;
    __syncthreads();
#pragma unroll
    for (int s = 128; s > 0; s >>= 1) {
        if (t < s) red[t] += red[t + s];
        __syncthreads();
    }
    const float inv = 1.f / red[0];

    alignas(16) uint32_t hw[4], lw[4];
#pragma unroll
    for (int c = 0; c < 8; c += 2) {
        float v0 = v[c] * inv, v1 = v[c + 1] * inv;
        __nv_bfloat16 h0 = __float2bfloat16(v0);
        __nv_bfloat16 h1 = __float2bfloat16(v1);
        __nv_bfloat16 l0 = __float2bfloat16(v0 - __bfloat162float(h0));
        __nv_bfloat16 l1 = __float2bfloat16(v1 - __bfloat162float(h1));
        hw[c >> 1] = (uint32_t)__bfloat16_as_ushort(h0) | ((uint32_t)__bfloat16_as_ushort(h1) << 16);
        lw[c >> 1] = (uint32_t)__bfloat16_as_ushort(l0) | ((uint32_t)__bfloat16_as_ushort(l1) << 16);
    }
    size_t base = (size_t)blockIdx.x * SEQ + t * 8;
    *(uint4*)(Ph + base) = *(const uint4*)(&hw[0]);
    *(uint4*)(Pl + base) = *(const uint4*)(&lw[0]);
}

// ---------------------------------------------------------------------------
// Launch
// ---------------------------------------------------------------------------
extern "C" void kernel_launch(void* const* d_in, const int* in_sizes, int n_in,
                              void* d_out, int out_size)
{
    const float* x  = (const float*)d_in[0];
    const float* Wq = (const float*)d_in[1];
    const float* bq = (const float*)d_in[2];
    const float* Wk = (const float*)d_in[3];
    const float* bk = (const float*)d_in[4];
    const float* Wv = (const float*)d_in[5];
    const float* bv = (const float*)d_in[6];
    float* out = (float*)d_out;

    cudaFuncSetAttribute((const void*)gemm_tc<0>, cudaFuncAttributeMaxDynamicSharedMemorySize, GEMM_SMEM);
    cudaFuncSetAttribute((const void*)gemm_tc<1>, cudaFuncAttributeMaxDynamicSharedMemorySize, GEMM_SMEM);
    cudaFuncSetAttribute((const void*)gemm_tc<2>, cudaFuncAttributeMaxDynamicSharedMemorySize, GEMM_SMEM);

    __nv_bfloat16 *xh, *xl, *Wqh, *Wql, *Wkh, *Wkl, *Wvh, *Wvl;
    __nv_bfloat16 *Qh, *Ql, *Kh, *Kl, *Vth, *Vtl, *Ph, *Pl;
    float* Sp;
    cudaGetSymbolAddress((void**)&xh, g_xh);   cudaGetSymbolAddress((void**)&xl, g_xl);
    cudaGetSymbolAddress((void**)&Wqh, g_Wqh); cudaGetSymbolAddress((void**)&Wql, g_Wql);
    cudaGetSymbolAddress((void**)&Wkh, g_Wkh); cudaGetSymbolAddress((void**)&Wkl, g_Wkl);
    cudaGetSymbolAddress((void**)&Wvh, g_Wvh); cudaGetSymbolAddress((void**)&Wvl, g_Wvl);
    cudaGetSymbolAddress((void**)&Qh, g_Qh);   cudaGetSymbolAddress((void**)&Ql, g_Ql);
    cudaGetSymbolAddress((void**)&Kh, g_Kh);   cudaGetSymbolAddress((void**)&Kl, g_Kl);
    cudaGetSymbolAddress((void**)&Vth, g_Vth); cudaGetSymbolAddress((void**)&Vtl, g_Vtl);
    cudaGetSymbolAddress((void**)&Ph, g_Ph);   cudaGetSymbolAddress((void**)&Pl, g_Pl);
    cudaGetSymbolAddress((void**)&Sp, g_S);

    const float qscale = 0.03125f;   // 1/sqrt(1024), exact power of two

    // 1) split inputs to bf16 hi/lo
    split_kernel<<<(size_t)BS * EMBED / 2048, 256>>>(x,  xh,  xl,  (size_t)BS * EMBED);
    split_kernel<<<EMBED * EMBED / 2048, 256>>>(Wq, Wqh, Wql, (size_t)EMBED * EMBED);
    split_kernel<<<EMBED * EMBED / 2048, 256>>>(Wk, Wkh, Wkl, (size_t)EMBED * EMBED);
    split_kernel<<<EMBED * EMBED / 2048, 256>>>(Wv, Wvh, Wvl, (size_t)EMBED * EMBED);

    // 2) Q = (x Wq^T + bq) * qscale ; K = x Wk^T + bk   (split bf16 out, col bias)
    {
        dim3 grid(EMBED / 128, BS / 128, 1);   // (8, 128)
        gemm_tc<1><<<grid, 256, GEMM_SMEM>>>(xh, xl, Wqh, Wql, bq, qscale,
                                             nullptr, Qh, Ql,
                                             EMBED, EMBED, EMBED, EMBED / 64, 0, 0, 0);
        gemm_tc<1><<<grid, 256, GEMM_SMEM>>>(xh, xl, Wkh, Wkl, bk, 1.0f,
                                             nullptr, Kh, Kl,
                                             EMBED, EMBED, EMBED, EMBED / 64, 0, 0, 0);
    }
    // 3) Vt[e, bs] = Wv x^T + bv  (row bias), ldc = BS
    {
        dim3 grid(BS / 128, EMBED / 128, 1);   // (128, 8)
        gemm_tc<2><<<grid, 256, GEMM_SMEM>>>(Wvh, Wvl, xh, xl, bv, 1.0f,
                                             nullptr, Vth, Vtl,
                                             EMBED, EMBED, BS, EMBED / 64, 0, 0, 0);
    }
    // 4) scores = Q K^T (scale already folded into Q), batched, fp32 out
    {
        dim3 grid(SEQ / 128, SEQ / 128, BATCH);   // (16, 16, 8)
        gemm_tc<0><<<grid, 256, GEMM_SMEM>>>(Qh, Ql, Kh, Kl, nullptr, 1.0f,
                                             Sp, nullptr, nullptr,
                                             EMBED, EMBED, SEQ, EMBED / 64,
                                             (long long)SEQ * EMBED,
                                             (long long)SEQ * EMBED,
                                             (long long)SEQ * SEQ);
    }
    // 5) softmax -> split bf16 P
    softmax_split<<<BATCH * SEQ, 256>>>(Sp, Ph, Pl);

    // 6) out = P V  (B = Vt rows, per-batch column window), fp32 out
    {
        dim3 grid(EMBED / 128, SEQ / 128, BATCH);   // (8, 16, 8)
        gemm_tc<0><<<grid, 256, GEMM_SMEM>>>(Ph, Pl, Vth, Vtl, nullptr, 1.0f,
                                             out, nullptr, nullptr,
                                             SEQ, BS, EMBED, SEQ / 64,
                                             (long long)SEQ * SEQ,
                                             (long long)SEQ,
                                             (long long)SEQ * EMBED);
    }
}

// round 4
// speedup vs baseline: 3.2624x; 1.0068x over previous
#include <cuda_runtime.h>
#include <cuda_bf16.h>
#include <cstdint>
#include <math.h>

// ---------------------------------------------------------------------------
// Problem constants
// ---------------------------------------------------------------------------
#define BATCH 8
#define SEQ   2048
#define EMBED 1024
#define BS    (BATCH * SEQ)          // 16384

// ---------------------------------------------------------------------------
// Device-global scratch (allocation-free rule)
// ---------------------------------------------------------------------------
__device__ __nv_bfloat16 g_xh[(size_t)BS * EMBED];
__device__ __nv_bfloat16 g_xl[(size_t)BS * EMBED];
__device__ __nv_bfloat16 g_Wqh[EMBED * EMBED], g_Wql[EMBED * EMBED];
__device__ __nv_bfloat16 g_Wkh[EMBED * EMBED], g_Wkl[EMBED * EMBED];
__device__ __nv_bfloat16 g_Wvh[EMBED * EMBED], g_Wvl[EMBED * EMBED];
__device__ __nv_bfloat16 g_Qh[(size_t)BS * EMBED], g_Ql[(size_t)BS * EMBED];
__device__ __nv_bfloat16 g_Kh[(size_t)BS * EMBED], g_Kl[(size_t)BS * EMBED];
// V stored pre-transposed: [EMBED rows][BS cols] (per-batch window of 2048 cols)
__device__ __nv_bfloat16 g_Vth[(size_t)EMBED * BS], g_Vtl[(size_t)EMBED * BS];
__device__ float         g_S[(size_t)BATCH * SEQ * SEQ];
__device__ __nv_bfloat16 g_Ph[(size_t)BATCH * SEQ * SEQ], g_Pl[(size_t)BATCH * SEQ * SEQ];

// ---------------------------------------------------------------------------
// Helpers
// ---------------------------------------------------------------------------
__device__ __forceinline__ uint32_t smem_u32(const void* p) {
    uint32_t a;
    asm("{ .reg .u64 t; cvta.to.shared.u64 t, %1; cvt.u32.u64 %0, t; }" : "=r"(a) : "l"(p));
    return a;
}

#define CP_ASYNC16(sm, gp) \
    asm volatile("cp.async.cg.shared.global [%0], [%1], 16;" :: "r"(sm), "l"(gp) : "memory")
#define CP_COMMIT()  asm volatile("cp.async.commit_group;" ::: "memory")
#define CP_WAIT0()   asm volatile("cp.async.wait_group 0;" ::: "memory")
#define CP_WAIT1()   asm volatile("cp.async.wait_group 1;" ::: "memory")

__device__ __forceinline__ void ldsm_x4(uint32_t* r, uint32_t addr) {
    asm volatile("ldmatrix.sync.aligned.m8n8.x4.shared.b16 {%0,%1,%2,%3}, [%4];"
                 : "=r"(r[0]), "=r"(r[1]), "=r"(r[2]), "=r"(r[3]) : "r"(addr));
}

__device__ __forceinline__ void mma16816(float* c, const uint32_t* a, const uint32_t* b) {
    asm volatile(
        "mma.sync.aligned.m16n8k16.row.col.f32.bf16.bf16.f32 "
        "{%0,%1,%2,%3}, {%4,%5,%6,%7}, {%8,%9}, {%0,%1,%2,%3};"
        : "+f"(c[0]), "+f"(c[1]), "+f"(c[2]), "+f"(c[3])
        : "r"(a[0]), "r"(a[1]), "r"(a[2]), "r"(a[3]), "r"(b[0]), "r"(b[1]));
}

// byte offset of 16B chunk (row, c) inside a [rows][64 bf16] tile, xor-swizzled
__device__ __forceinline__ uint32_t swz(int row, int c) {
    return (uint32_t)((row * 8 + (c ^ (row & 7))) * 16);
}

// ---------------------------------------------------------------------------
// HMMA GEMM NT: C[M,N] = A[M,K] * B[N,K]^T, two-term bf16 split operands
//   D += AhBh + AhBl + AlBh (fp32 accum in registers)
// CTA tile 128x256, warp tile 64x64 (8 warps, 2x4), K-chunk 64,
// double-buffered cp.async SMEM pipeline (96KB/stage).
// MODE 0: C = fp32 -> Cf
// MODE 1: v = (acc + bias[col]) * scale; split -> Ch/Cl. blockIdx.z selects
//         operand-set {Bh,Bl,bias,scale,Ch,Cl} (z=0) or the "2" set (z=1).
// MODE 2: v = (acc + bias[row]) * scale; split -> Ch/Cl (bf16)
// ---------------------------------------------------------------------------
#define STAGE_BYTES 98304
#define A_H_OFF 0
#define A_L_OFF 16384
#define B_H_OFF 32768
#define B_L_OFF 65536
#define GEMM_SMEM (2 * STAGE_BYTES)

template <int MODE>
__global__ void __launch_bounds__(256, 1)
gemm_tc(const __nv_bfloat16* __restrict__ Ah, const __nv_bfloat16* __restrict__ Al,
        const __nv_bfloat16* Bh, const __nv_bfloat16* Bl,
        const float* bias, float scale,
        float* __restrict__ Cf, __nv_bfloat16* Ch, __nv_bfloat16* Cl,
        int lda, int ldb, int ldc, int nchunk,
        long long strideA, long long strideB, long long strideC,
        const __nv_bfloat16* Bh2, const __nv_bfloat16* Bl2,
        const float* bias2, float scale2,
        __nv_bfloat16* Ch2, __nv_bfloat16* Cl2)
{
    extern __shared__ char smem[];
    const uint32_t sbase = smem_u32(smem);
    const int tid = threadIdx.x;
    const int wid = tid >> 5;
    const int lane = tid & 31;
    const int wm = wid & 1;          // 0..1  M direction (64 rows each)
    const int wn = wid >> 1;         // 0..3  N direction (64 cols each)

    const long long z = blockIdx.z;
    if (MODE == 1) {
        if (z == 1) {
            Bh = Bh2; Bl = Bl2; bias = bias2; scale = scale2; Ch = Ch2; Cl = Cl2;
        }
    } else {
        Ah += z * strideA;  Al += z * strideA;
        Bh += z * strideB;  Bl += z * strideB;
    }

    const int rowA0 = blockIdx.y * 128;
    const int colB0 = blockIdx.x * 256;

    float acc[4][8][4];
#pragma unroll
    for (int mt = 0; mt < 4; mt++)
#pragma unroll
        for (int nt = 0; nt < 8; nt++)
#pragma unroll
            for (int r = 0; r < 4; r++) acc[mt][nt][r] = 0.f;

    const __nv_bfloat16* gAh = Ah + (size_t)rowA0 * lda;
    const __nv_bfloat16* gAl = Al + (size_t)rowA0 * lda;
    const __nv_bfloat16* gBh = Bh + (size_t)colB0 * ldb;
    const __nv_bfloat16* gBl = Bl + (size_t)colB0 * ldb;

    // issue all cp.async for one stage: A 128x64 (h+l), B 256x64 (h+l)
    auto issue_stage = [&](int kc, int stg) {
        const uint32_t sb = sbase + stg * STAGE_BYTES;
        const int k0 = kc * 64;
#pragma unroll
        for (int it = 0; it < 4; it++) {
            int idx = it * 256 + tid;
            int r = idx >> 3, c = idx & 7;
            uint32_t so = swz(r, c);
            CP_ASYNC16(sb + A_H_OFF + so, gAh + (size_t)r * lda + k0 + c * 8);
            CP_ASYNC16(sb + A_L_OFF + so, gAl + (size_t)r * lda + k0 + c * 8);
        }
#pragma unroll
        for (int it = 0; it < 8; it++) {
            int idx = it * 256 + tid;
            int r = idx >> 3, c = idx & 7;
            uint32_t so = swz(r, c);
            CP_ASYNC16(sb + B_H_OFF + so, gBh + (size_t)r * ldb + k0 + c * 8);
            CP_ASYNC16(sb + B_L_OFF + so, gBl + (size_t)r * ldb + k0 + c * 8);
        }
    };

    issue_stage(0, 0);
    CP_COMMIT();

    // ldmatrix lane address components
    const int a_row = lane & 15;                         // row within 16-row m-tile
    const int a_csel = lane >> 4;                        // 0/1 -> 8-col halves
    const int b_row = (lane & 7) + ((lane >> 4) << 3);   // row within 16-row n-tile
    const int b_csel = (lane >> 3) & 1;

    for (int kc = 0; kc < nchunk; kc++) {
        const int stg = kc & 1;
        if (kc + 1 < nchunk) {
            issue_stage(kc + 1, stg ^ 1);
            CP_COMMIT();
            CP_WAIT1();
        } else {
            CP_WAIT0();
        }
        __syncthreads();

        const uint32_t sb = sbase + stg * STAGE_BYTES;
        const uint32_t aH = sb + A_H_OFF, aL = sb + A_L_OFF;
        const uint32_t bH = sb + B_H_OFF, bL = sb + B_L_OFF;

#pragma unroll
        for (int ks = 0; ks < 4; ks++) {
            uint32_t fAh[4][4], fAl[4][4], fBh[4][4], fBl[4][4];
            const int kchunk = ks * 2;
#pragma unroll
            for (int mt = 0; mt < 4; mt++) {
                int mr = wm * 64 + mt * 16 + a_row;
                uint32_t off = swz(mr, kchunk + a_csel);
                ldsm_x4(fAh[mt], aH + off);
                ldsm_x4(fAl[mt], aL + off);
            }
#pragma unroll
            for (int g = 0; g < 4; g++) {
                int nr = wn * 64 + g * 16 + b_row;
                uint32_t off = swz(nr, kchunk + b_csel);
                ldsm_x4(fBh[g], bH + off);
                ldsm_x4(fBl[g], bL + off);
            }
#pragma unroll
            for (int mt = 0; mt < 4; mt++)
#pragma unroll
                for (int nt = 0; nt < 8; nt++) {
                    const uint32_t* bh = &fBh[nt >> 1][(nt & 1) * 2];
                    const uint32_t* bl = &fBl[nt >> 1][(nt & 1) * 2];
                    mma16816(acc[mt][nt], fAh[mt], bh);
                    mma16816(acc[mt][nt], fAh[mt], bl);
                    mma16816(acc[mt][nt], fAl[mt], bh);
                }
        }
        __syncthreads();
    }

    // ------------------------------ epilogue ------------------------------
    const int lrow = (lane >> 2);        // 0..7
    const int lcol = (lane & 3) * 2;     // 0,2,4,6

#pragma unroll
    for (int mt = 0; mt < 4; mt++) {
#pragma unroll
        for (int half = 0; half < 2; half++) {
            const int row = rowA0 + wm * 64 + mt * 16 + lrow + half * 8;
            float rb = (MODE == 2) ? bias[row] : 0.f;
#pragma unroll
            for (int nt = 0; nt < 8; nt++) {
                const int col = colB0 + wn * 64 + nt * 8 + lcol;
                float v0 = acc[mt][nt][half * 2 + 0];
                float v1 = acc[mt][nt][half * 2 + 1];
                if (MODE == 0) {
                    float2 o = make_float2(v0, v1);
                    *(float2*)(Cf + z * strideC + (size_t)row * ldc + col) = o;
                } else {
                    if (MODE == 1) { v0 = (v0 + bias[col]) * scale; v1 = (v1 + bias[col + 1]) * scale; }
                    else           { v0 = (v0 + rb) * scale;       v1 = (v1 + rb) * scale; }
                    __nv_bfloat16 h0 = __float2bfloat16(v0);
                    __nv_bfloat16 h1 = __float2bfloat16(v1);
                    __nv_bfloat16 l0 = __float2bfloat16(v0 - __bfloat162float(h0));
                    __nv_bfloat16 l1 = __float2bfloat16(v1 - __bfloat162float(h1));
                    uint32_t hw = (uint32_t)__bfloat16_as_ushort(h0) |
                                  ((uint32_t)__bfloat16_as_ushort(h1) << 16);
                    uint32_t lw = (uint32_t)__bfloat16_as_ushort(l0) |
                                  ((uint32_t)__bfloat16_as_ushort(l1) << 16);
                    *(uint32_t*)(Ch + (size_t)row * ldc + col) = hw;
                    *(uint32_t*)(Cl + (size_t)row * ldc + col) = lw;
                }
            }
        }
    }
}

// ---------------------------------------------------------------------------
// fp32 -> (bf16 hi, bf16 lo) split
// ---------------------------------------------------------------------------
__global__ void __launch_bounds__(256, 8)
split_kernel(const float* __restrict__ in, __nv_bfloat16* __restrict__ hi,
             __nv_bfloat16* __restrict__ lo, size_t n)
{
    size_t i = ((size_t)blockIdx.x * blockDim.x + threadIdx.x) * 8;
    if (i >= n) return;
    float4 a = *(const float4*)(in + i);
    float4 b = *(const float4*)(in + i + 4);
    float v[8] = {a.x, a.y, a.z, a.w, b.x, b.y, b.z, b.w};
    alignas(16) uint32_t hw[4], lw[4];
#pragma unroll
    for (int c = 0; c < 8; c += 2) {
        __nv_bfloat16 h0 = __float2bfloat16(v[c]);
        __nv_bfloat16 h1 = __float2bfloat16(v[c + 1]);
        __nv_bfloat16 l0 = __float2bfloat16(v[c] - __bfloat162float(h0));
        __nv_bfloat16 l1 = __float2bfloat16(v[c + 1] - __bfloat162float(h1));
        hw[c >> 1] = (uint32_t)__bfloat16_as_ushort(h0) | ((uint32_t)__bfloat16_as_ushort(h1) << 16);
        lw[c >> 1] = (uint32_t)__bfloat16_as_ushort(l0) | ((uint32_t)__bfloat16_as_ushort(l1) << 16);
    }
    *(uint4*)(hi + i) = *(const uint4*)(&hw[0]);
    *(uint4*)(lo + i) = *(const uint4*)(&lw[0]);
}

// ---------------------------------------------------------------------------
// Row softmax (fp32 in) -> split bf16 out. One block per row of SEQ floats.
// ---------------------------------------------------------------------------
__global__ void __launch_bounds__(256, 4)
softmax_split(const float* __restrict__ Sm, __nv_bfloat16* __restrict__ Ph,
              __nv_bfloat16* __restrict__ Pl)
{
    const float* row = Sm + (size_t)blockIdx.x * SEQ;
    const int t = threadIdx.x;

    float v[8];
    *(float4*)(v + 0) = *(const float4*)(row + t * 8 + 0);
    *(float4*)(v + 4) = *(const float4*)(row + t * 8 + 4);

    float mx = v[0];
#pragma unroll
    for (int i = 1; i < 8; i++) mx = fmaxf(mx, v[i]);

    __shared__ float red[256];
    red[t] = mx;
    __syncthreads();
#pragma unroll
    for (int s = 128; s > 0; s >>= 1) {
        if (t < s) red[t] = fmaxf(red[t], red[t + s]);
        __syncthreads();
    }
    mx = red[0];
    __syncthreads();

    float sum = 0.f;
#pragma unroll
    for (int i = 0; i < 8; i++) {
        v[i] = __expf(v[i] - mx);
        sum += v[i];
    }
    red[t] = sum;
    __syncthreads();
#pragma unroll
    for (int s = 128; s > 0; s >>= 1) {
        if (t < s) red[t] += red[t + s];
        __syncthreads();
    }
    const float inv = 1.f / red[0];

    alignas(16) uint32_t hw[4], lw[4];
#pragma unroll
    for (int c = 0; c < 8; c += 2) {
        float v0 = v[c] * inv, v1 = v[c + 1] * inv;
        __nv_bfloat16 h0 = __float2bfloat16(v0);
        __nv_bfloat16 h1 = __float2bfloat16(v1);
        __nv_bfloat16 l0 = __float2bfloat16(v0 - __bfloat162float(h0));
        __nv_bfloat16 l1 = __float2bfloat16(v1 - __bfloat162float(h1));
        hw[c >> 1] = (uint32_t)__bfloat16_as_ushort(h0) | ((uint32_t)__bfloat16_as_ushort(h1) << 16);
        lw[c >> 1] = (uint32_t)__bfloat16_as_ushort(l0) | ((uint32_t)__bfloat16_as_ushort(l1) << 16);
    }
    size_t base = (size_t)blockIdx.x * SEQ + t * 8;
    *(uint4*)(Ph + base) = *(const uint4*)(&hw[0]);
    *(uint4*)(Pl + base) = *(const uint4*)(&lw[0]);
}

// ---------------------------------------------------------------------------
// Launch
// ---------------------------------------------------------------------------
extern "C" void kernel_launch(void* const* d_in, const int* in_sizes, int n_in,
                              void* d_out, int out_size)
{
    const float* x  = (const float*)d_in[0];
    const float* Wq = (const float*)d_in[1];
    const float* bq = (const float*)d_in[2];
    const float* Wk = (const float*)d_in[3];
    const float* bk = (const float*)d_in[4];
    const float* Wv = (const float*)d_in[5];
    const float* bv = (const float*)d_in[6];
    float* out = (float*)d_out;

    cudaFuncSetAttribute((const void*)gemm_tc<0>, cudaFuncAttributeMaxDynamicSharedMemorySize, GEMM_SMEM);
    cudaFuncSetAttribute((const void*)gemm_tc<1>, cudaFuncAttributeMaxDynamicSharedMemorySize, GEMM_SMEM);
    cudaFuncSetAttribute((const void*)gemm_tc<2>, cudaFuncAttributeMaxDynamicSharedMemorySize, GEMM_SMEM);

    __nv_bfloat16 *xh, *xl, *Wqh, *Wql, *Wkh, *Wkl, *Wvh, *Wvl;
    __nv_bfloat16 *Qh, *Ql, *Kh, *Kl, *Vth, *Vtl, *Ph, *Pl;
    float* Sp;
    cudaGetSymbolAddress((void**)&xh, g_xh);   cudaGetSymbolAddress((void**)&xl, g_xl);
    cudaGetSymbolAddress((void**)&Wqh, g_Wqh); cudaGetSymbolAddress((void**)&Wql, g_Wql);
    cudaGetSymbolAddress((void**)&Wkh, g_Wkh); cudaGetSymbolAddress((void**)&Wkl, g_Wkl);
    cudaGetSymbolAddress((void**)&Wvh, g_Wvh); cudaGetSymbolAddress((void**)&Wvl, g_Wvl);
    cudaGetSymbolAddress((void**)&Qh, g_Qh);   cudaGetSymbolAddress((void**)&Ql, g_Ql);
    cudaGetSymbolAddress((void**)&Kh, g_Kh);   cudaGetSymbolAddress((void**)&Kl, g_Kl);
    cudaGetSymbolAddress((void**)&Vth, g_Vth); cudaGetSymbolAddress((void**)&Vtl, g_Vtl);
    cudaGetSymbolAddress((void**)&Ph, g_Ph);   cudaGetSymbolAddress((void**)&Pl, g_Pl);
    cudaGetSymbolAddress((void**)&Sp, g_S);

    const float qscale = 0.03125f;   // 1/sqrt(1024), exact power of two

    // 1) split inputs to bf16 hi/lo
    split_kernel<<<(size_t)BS * EMBED / 2048, 256>>>(x,  xh,  xl,  (size_t)BS * EMBED);
    split_kernel<<<EMBED * EMBED / 2048, 256>>>(Wq, Wqh, Wql, (size_t)EMBED * EMBED);
    split_kernel<<<EMBED * EMBED / 2048, 256>>>(Wk, Wkh, Wkl, (size_t)EMBED * EMBED);
    split_kernel<<<EMBED * EMBED / 2048, 256>>>(Wv, Wvh, Wvl, (size_t)EMBED * EMBED);

    // 2) Q = (x Wq^T + bq) * qscale  (z=0) ;  K = x Wk^T + bk  (z=1)
    {
        dim3 grid(EMBED / 256, BS / 128, 2);   // (4, 128, 2)
        gemm_tc<1><<<grid, 256, GEMM_SMEM>>>(xh, xl, Wqh, Wql, bq, qscale,
                                             nullptr, Qh, Ql,
                                             EMBED, EMBED, EMBED, EMBED / 64, 0, 0, 0,
                                             Wkh, Wkl, bk, 1.0f, Kh, Kl);
    }
    // 3) Vt[e, bs] = Wv x^T + bv  (row bias), ldc = BS
    {
        dim3 grid(BS / 256, EMBED / 128, 1);   // (64, 8)
        gemm_tc<2><<<grid, 256, GEMM_SMEM>>>(Wvh, Wvl, xh, xl, bv, 1.0f,
                                             nullptr, Vth, Vtl,
                                             EMBED, EMBED, BS, EMBED / 64, 0, 0, 0,
                                             nullptr, nullptr, nullptr, 0.f, nullptr, nullptr);
    }
    // 4) scores = Q K^T (scale already folded into Q), batched, fp32 out
    {
        dim3 grid(SEQ / 256, SEQ / 128, BATCH);   // (8, 16, 8)
        gemm_tc<0><<<grid, 256, GEMM_SMEM>>>(Qh, Ql, Kh, Kl, nullptr, 1.0f,
                                             Sp, nullptr, nullptr,
                                             EMBED, EMBED, SEQ, EMBED / 64,
                                             (long long)SEQ * EMBED,
                                             (long long)SEQ * EMBED,
                                             (long long)SEQ * SEQ,
                                             nullptr, nullptr, nullptr, 0.f, nullptr, nullptr);
    }
    // 5) softmax -> split bf16 P
    softmax_split<<<BATCH * SEQ, 256>>>(Sp, Ph, Pl);

    // 6) out = P V  (B = Vt rows, per-batch column window), fp32 out
    {
        dim3 grid(EMBED / 256, SEQ / 128, BATCH);   // (4, 16, 8)
        gemm_tc<0><<<grid, 256, GEMM_SMEM>>>(Ph, Pl, Vth, Vtl, nullptr, 1.0f,
                                             out, nullptr, nullptr,
                                             SEQ, BS, EMBED, SEQ / 64,
                                             (long long)SEQ * SEQ,
                                             (long long)SEQ,
                                             (long long)SEQ * EMBED,
                                             nullptr, nullptr, nullptr, 0.f, nullptr, nullptr);
    }
}